// round 15
// baseline (speedup 1.0000x reference)
#include <cuda_runtime.h>

#define BB 4
#define NPTS 2048
#define HH 128
#define WW 128
#define SPLITS 32
#define KCH (NPTS / SPLITS)   // 64 atoms per (s,b)
#define CHUNK 32              // atoms resident in shared at once
#define IMG (BB * HH * WW)    // 65536
#define IMG4 (IMG / 4)        // 16384
#define IMGB (HH * WW)        // 16384

// Cutoff radius: |d| < 7 -> exp(-49/4.5) = 1.8e-5 tail (measured rel_err 7.2e-6)
#define RCUT   7.0f
#define RCUT2  49.0f

// Split-K partials: 32 * 256KB = 8 MB (no device allocations allowed)
__device__ float g_part[SPLITS * BB * HH * WW];

// ---------------------------------------------------------------------------
// Fused kernel, column-QUARTERED. Block (s, b, qt) accumulates its 64 atoms
// into output columns [32*qt, 32*qt+32). Grid = 512 CTAs (~3.5/SM). Warp w
// owns rows [16w, 16w+16); thread tile 8 rows x 2 cols. Atom processed only
// if its y-support hits the warp's window AND its x-support hits this column
// quarter (skipped atoms are exactly zero on this tile under the cutoff).
// ---------------------------------------------------------------------------
__global__ void __launch_bounds__(256, 3) fused_kernel(const float* __restrict__ x,
                                                       const float* __restrict__ rot) {
    int s  = blockIdx.x;
    int b  = blockIdx.y;
    int qt = blockIdx.z;             // column quarter (0..3)
    float colbase = 32.0f * qt;

    __shared__ float sfy[CHUNK][128];   // 16KB  (all rows)
    __shared__ float sfx[CHUNK][32];    // 4KB   (this quarter's cols)
    __shared__ float spx[CHUNK];
    __shared__ float spy[CHUNK];
    __shared__ unsigned swm[8];         // per-row-window atom bitmap
    __shared__ unsigned sxm;            // this-quarter atom bitmap

    int tid  = threadIdx.x;
    int w    = tid >> 5;      // warp id = 16-row window (0..7)
    int lane = tid & 31;
    int rg   = lane >> 4;     // row sub-group: rows 16w+8rg .. +8
    int cx   = lane & 15;     // 2-col group within the 32-col quarter

    const float* R = rot + b * 9;
    float R0 = R[0], R1 = R[1], R2 = R[2];
    float R3 = R[3], R4 = R[4], R5 = R[5];

    float acc[8][2];
#pragma unroll
    for (int i = 0; i < 8; i++) { acc[i][0] = 0.0f; acc[i][1] = 0.0f; }

    int atom_base = b * NPTS + s * KCH;

    for (int c = 0; c < KCH / CHUNK; c++) {
        // --- Phase A: warp 0 projects 32 atoms, builds bitmaps ---
        if (tid < 32) {
            const float* xp = x + (atom_base + c * CHUNK + tid) * 3;
            float x0 = xp[0], x1 = xp[1], x2 = xp[2];
            const float scale = 51.2f;
            float px = fmaf(R0, x0, fmaf(R1, x1, R2 * x2)) * scale + 64.0f;
            float py = fmaf(R3, x0, fmaf(R4, x1, R5 * x2)) * scale + 64.0f;
            spx[tid] = px;
            spy[tid] = py;
            int w0 = (int)floorf((py - RCUT) * 0.0625f);
            int w1 = (int)floorf((py + RCUT) * 0.0625f);
            if (w0 < 0) w0 = 0;
            if (w1 > 7) w1 = 7;
#pragma unroll
            for (int ww = 0; ww < 8; ww++) {
                unsigned bm = __ballot_sync(0xffffffffu, ww >= w0 && ww <= w1);
                if (tid == ww) swm[ww] = bm;
            }
            unsigned hx = __ballot_sync(0xffffffffu,
                                        px > colbase - RCUT &&
                                        px < colbase + 31.0f + RCUT);
            if (tid == 0) sxm = hx;
        }
        __syncthreads();

        // --- Phase B: factor tables (truncated Gaussians) ---
        const float cexp = -0.22222222f;  // -1/(2*1.5^2)
#pragma unroll 4
        for (int i = 0; i < 16; i++) {    // sfy: 32x128 entries
            int e = tid + i * 256;
            int a = e >> 7;
            int p = e & 127;
            float dy = (float)p - spy[a];
            float qy = dy * dy;
            sfy[a][p] = (qy < RCUT2) ? __expf(qy * cexp) : 0.0f;
        }
#pragma unroll
        for (int i = 0; i < 4; i++) {     // sfx: 32x32 entries (this quarter)
            int e = tid + i * 256;
            int a = e >> 5;
            int pl = e & 31;
            float dx = (colbase + (float)pl) - spx[a];
            float qx = dx * dx;
            sfx[a][pl] = (qx < RCUT2) ? __expf(qx * cexp) : 0.0f;
        }
        __syncthreads();

        // --- Phase C: sparse rank update ---
        unsigned m = swm[w] & sxm;
        int rowbase = 16 * w + 8 * rg;
        while (m) {
            int kk = __ffs(m) - 1;
            m &= m - 1;
            float yv[8], xv[2];
            *(float4*)&yv[0] = *(float4*)&sfy[kk][rowbase];      // broadcast
            *(float4*)&yv[4] = *(float4*)&sfy[kk][rowbase + 4];
            *(float2*)&xv[0] = *(float2*)&sfx[kk][cx * 2];
#pragma unroll
            for (int i = 0; i < 8; i++) {
                acc[i][0] = fmaf(yv[i], xv[0], acc[i][0]);
                acc[i][1] = fmaf(yv[i], xv[1], acc[i][1]);
            }
        }
        __syncthreads();
    }

    // --- Epilogue: store this quarter's partial tile ---
    float* out = g_part + (s * BB + b) * IMGB + 32 * qt;
#pragma unroll
    for (int i = 0; i < 8; i++) {
        int h = 16 * w + 8 * rg + i;
        *(float2*)&out[h * WW + cx * 2] = make_float2(acc[i][0], acc[i][1]);
    }
}

// ---------------------------------------------------------------------------
// Combine (best measured shape): 8 threads per output float4, 4 splits each,
// butterfly-shuffle reduction; 512 blocks.
// ---------------------------------------------------------------------------
__global__ void __launch_bounds__(256) combine_kernel(const float* __restrict__ noise,
                                                      const float* __restrict__ rot,
                                                      float* __restrict__ out) {
    int tid  = threadIdx.x;
    int lane = tid & 31;
    int wp   = tid >> 5;
    int o = blockIdx.x * 32 + wp * 4 + (lane & 3);   // output float4 idx
    int g = lane >> 2;                               // split group 0..7

    const float4* p = (const float4*)g_part;
    float4 v0 = __ldcg(p + (g * 4 + 0) * IMG4 + o);
    float4 v1 = __ldcg(p + (g * 4 + 1) * IMG4 + o);
    float4 v2 = __ldcg(p + (g * 4 + 2) * IMG4 + o);
    float4 v3 = __ldcg(p + (g * 4 + 3) * IMG4 + o);
    float4 s;
    s.x = (v0.x + v1.x) + (v2.x + v3.x);
    s.y = (v0.y + v1.y) + (v2.y + v3.y);
    s.z = (v0.z + v1.z) + (v2.z + v3.z);
    s.w = (v0.w + v1.w) + (v2.w + v3.w);

#pragma unroll
    for (int off = 4; off <= 16; off <<= 1) {
        s.x += __shfl_xor_sync(0xffffffffu, s.x, off);
        s.y += __shfl_xor_sync(0xffffffffu, s.y, off);
        s.z += __shfl_xor_sync(0xffffffffu, s.z, off);
        s.w += __shfl_xor_sync(0xffffffffu, s.w, off);
    }

    if (g == 0) {
        float4 nz = ((const float4*)noise)[o];
        float4 noisy = make_float4(fmaf(nz.x, 0.1f, s.x), fmaf(nz.y, 0.1f, s.y),
                                   fmaf(nz.z, 0.1f, s.z), fmaf(nz.w, 0.1f, s.w));
        ((float4*)out)[o] = noisy;                 // noisy
        *(float4*)&out[IMG + 36 + o * 4] = s;      // clean (65572 % 4 == 0)
    }
    if (blockIdx.x == 0 && tid < 36) out[IMG + tid] = rot[tid];
}

// ---------------------------------------------------------------------------
extern "C" void kernel_launch(void* const* d_in, const int* in_sizes, int n_in,
                              void* d_out, int out_size) {
    const float* x     = (const float*)d_in[0];  // (4,2048,3)
    const float* rot   = (const float*)d_in[1];  // (4,3,3)
    const float* noise = (const float*)d_in[2];  // (4,128,128)
    float* out = (float*)d_out;

    dim3 grid(SPLITS, BB, 4);                    // 512 CTAs
    fused_kernel<<<grid, 256>>>(x, rot);

    combine_kernel<<<IMG4 / 32, 256>>>(noise, rot, out);
}

// round 16
// speedup vs baseline: 1.4504x; 1.4504x over previous
#include <cuda_runtime.h>

#define BB 4
#define NPTS 2048
#define HH 128
#define WW 128
#define SPLITS 32
#define KCH (NPTS / SPLITS)   // 64 atoms per (s,b)
#define CHUNK 32              // atoms resident in shared at once
#define IMG (BB * HH * WW)    // 65536
#define IMG4 (IMG / 4)        // 16384
#define IMGB (HH * WW)        // 16384

// Cutoff radius: |d| < 7 -> exp(-49/4.5) = 1.8e-5 tail (measured rel_err 7.2e-6)
#define RCUT   7.0f
#define RCUT2  49.0f

// Split-K partials: 32 * 256KB = 8 MB (no device allocations allowed)
__device__ float g_part[SPLITS * BB * HH * WW];

// ---------------------------------------------------------------------------
// Fused kernel, column-halved, SPARSE Phase B. Block (s, b, hf): 64 atoms
// into columns [64*hf, +64). Tables are zeroed with STS.128 (overlapped with
// Phase A projection), then only each atom's <=14-wide support window is
// filled (8 threads per atom, 2+2 slots each). Unwritten entries stay zero --
// identical values to the dense fill. Phase C unchanged (sparse rank update).
// ---------------------------------------------------------------------------
__global__ void __launch_bounds__(256) fused_kernel(const float* __restrict__ x,
                                                    const float* __restrict__ rot) {
    int s  = blockIdx.x;
    int b  = blockIdx.y;
    int hf = blockIdx.z;             // column half (0/1)
    int   colbase_i = 64 * hf;
    float colbase   = (float)colbase_i;

    __shared__ float sfy[CHUNK][128];   // 16KB  (all rows)
    __shared__ float sfx[CHUNK][64];    // 8KB   (this half's cols)
    __shared__ float spx[CHUNK];
    __shared__ float spy[CHUNK];
    __shared__ unsigned swm[8];         // per-row-window atom bitmap
    __shared__ unsigned sxm;            // this-half atom bitmap

    int tid  = threadIdx.x;
    int w    = tid >> 5;      // warp id = 16-row window (0..7)
    int lane = tid & 31;
    int rg   = lane >> 4;     // row sub-group: rows 16w+8rg .. +8
    int cx   = lane & 15;     // 4-col group within the 64-col half

    const float* R = rot + b * 9;
    float R0 = R[0], R1 = R[1], R2 = R[2];
    float R3 = R[3], R4 = R[4], R5 = R[5];

    float acc[8][4];
#pragma unroll
    for (int i = 0; i < 8; i++)
#pragma unroll
        for (int j = 0; j < 4; j++) acc[i][j] = 0.0f;

    int atom_base = b * NPTS + s * KCH;
    const float cexp = -0.22222222f;  // -1/(2*1.5^2)

    for (int c = 0; c < KCH / CHUNK; c++) {
        // --- Phase A (warp 0) + table zeroing (all threads), one sync ---
        {
            float4 z4 = make_float4(0.f, 0.f, 0.f, 0.f);
            float4* zy = (float4*)&sfy[0][0];    // 1024 float4
            float4* zx = (float4*)&sfx[0][0];    // 512 float4
#pragma unroll
            for (int i = 0; i < 4; i++) zy[tid + i * 256] = z4;
#pragma unroll
            for (int i = 0; i < 2; i++) zx[tid + i * 256] = z4;
        }
        if (tid < 32) {
            const float* xp = x + (atom_base + c * CHUNK + tid) * 3;
            float x0 = xp[0], x1 = xp[1], x2 = xp[2];
            const float scale = 51.2f;
            float px = fmaf(R0, x0, fmaf(R1, x1, R2 * x2)) * scale + 64.0f;
            float py = fmaf(R3, x0, fmaf(R4, x1, R5 * x2)) * scale + 64.0f;
            spx[tid] = px;
            spy[tid] = py;
            int w0 = (int)floorf((py - RCUT) * 0.0625f);
            int w1 = (int)floorf((py + RCUT) * 0.0625f);
            if (w0 < 0) w0 = 0;
            if (w1 > 7) w1 = 7;
#pragma unroll
            for (int ww = 0; ww < 8; ww++) {
                unsigned bm = __ballot_sync(0xffffffffu, ww >= w0 && ww <= w1);
                if (tid == ww) swm[ww] = bm;
            }
            unsigned hx = __ballot_sync(0xffffffffu,
                                        px > colbase - RCUT &&
                                        px < colbase + 63.0f + RCUT);
            if (tid == 0) sxm = hx;
        }
        __syncthreads();

        // --- Phase B: sparse window fill. 8 threads per atom; support is at
        //     most 14 integer pixels wide, covered by slots {j, j+8}. ---
        {
            int a = tid >> 3;             // atom 0..31
            int j = tid & 7;
            float py = spy[a];
            int basey = (int)ceilf(py - RCUT);
#pragma unroll
            for (int k = 0; k < 2; k++) {
                int p = basey + j + k * 8;
                if (p >= 0 && p < 128) {
                    float dy = (float)p - py;
                    float q = dy * dy;
                    if (q < RCUT2) sfy[a][p] = __expf(q * cexp);
                }
            }
            float px = spx[a];
            int basex = (int)ceilf(px - RCUT);
#pragma unroll
            for (int k = 0; k < 2; k++) {
                int g = basex + j + k * 8;
                int pl = g - colbase_i;
                if (pl >= 0 && pl < 64) {
                    float dx = (float)g - px;
                    float q = dx * dx;
                    if (q < RCUT2) sfx[a][pl] = __expf(q * cexp);
                }
            }
        }
        __syncthreads();

        // --- Phase C: sparse rank update ---
        unsigned m = swm[w] & sxm;
        int rowbase = 16 * w + 8 * rg;
        while (m) {
            int kk = __ffs(m) - 1;
            m &= m - 1;
            float yv[8], xv[4];
            *(float4*)&yv[0] = *(float4*)&sfy[kk][rowbase];      // broadcast
            *(float4*)&yv[4] = *(float4*)&sfy[kk][rowbase + 4];
            *(float4*)&xv[0] = *(float4*)&sfx[kk][cx * 4];
#pragma unroll
            for (int i = 0; i < 8; i++)
#pragma unroll
                for (int j = 0; j < 4; j++)
                    acc[i][j] = fmaf(yv[i], xv[j], acc[i][j]);
        }
        __syncthreads();
    }

    // --- Epilogue: store this half's partial tile ---
    float* out = g_part + (s * BB + b) * IMGB + colbase_i;
#pragma unroll
    for (int i = 0; i < 8; i++) {
        int h = 16 * w + 8 * rg + i;
        float4 v = make_float4(acc[i][0], acc[i][1], acc[i][2], acc[i][3]);
        *(float4*)&out[h * WW + cx * 4] = v;
    }
}

// ---------------------------------------------------------------------------
// Combine (best measured shape): 8 threads per output float4, 4 splits each,
// butterfly-shuffle reduction; 512 blocks.
// ---------------------------------------------------------------------------
__global__ void __launch_bounds__(256) combine_kernel(const float* __restrict__ noise,
                                                      const float* __restrict__ rot,
                                                      float* __restrict__ out) {
    int tid  = threadIdx.x;
    int lane = tid & 31;
    int wp   = tid >> 5;
    int o = blockIdx.x * 32 + wp * 4 + (lane & 3);   // output float4 idx
    int g = lane >> 2;                               // split group 0..7

    const float4* p = (const float4*)g_part;
    float4 v0 = __ldcg(p + (g * 4 + 0) * IMG4 + o);
    float4 v1 = __ldcg(p + (g * 4 + 1) * IMG4 + o);
    float4 v2 = __ldcg(p + (g * 4 + 2) * IMG4 + o);
    float4 v3 = __ldcg(p + (g * 4 + 3) * IMG4 + o);
    float4 s;
    s.x = (v0.x + v1.x) + (v2.x + v3.x);
    s.y = (v0.y + v1.y) + (v2.y + v3.y);
    s.z = (v0.z + v1.z) + (v2.z + v3.z);
    s.w = (v0.w + v1.w) + (v2.w + v3.w);

#pragma unroll
    for (int off = 4; off <= 16; off <<= 1) {
        s.x += __shfl_xor_sync(0xffffffffu, s.x, off);
        s.y += __shfl_xor_sync(0xffffffffu, s.y, off);
        s.z += __shfl_xor_sync(0xffffffffu, s.z, off);
        s.w += __shfl_xor_sync(0xffffffffu, s.w, off);
    }

    if (g == 0) {
        float4 nz = ((const float4*)noise)[o];
        float4 noisy = make_float4(fmaf(nz.x, 0.1f, s.x), fmaf(nz.y, 0.1f, s.y),
                                   fmaf(nz.z, 0.1f, s.z), fmaf(nz.w, 0.1f, s.w));
        ((float4*)out)[o] = noisy;                 // noisy
        *(float4*)&out[IMG + 36 + o * 4] = s;      // clean (65572 % 4 == 0)
    }
    if (blockIdx.x == 0 && tid < 36) out[IMG + tid] = rot[tid];
}

// ---------------------------------------------------------------------------
extern "C" void kernel_launch(void* const* d_in, const int* in_sizes, int n_in,
                              void* d_out, int out_size) {
    const float* x     = (const float*)d_in[0];  // (4,2048,3)
    const float* rot   = (const float*)d_in[1];  // (4,3,3)
    const float* noise = (const float*)d_in[2];  // (4,128,128)
    float* out = (float*)d_out;

    dim3 grid(SPLITS, BB, 2);                    // 256 CTAs (best measured)
    fused_kernel<<<grid, 256>>>(x, rot);

    combine_kernel<<<IMG4 / 32, 256>>>(noise, rot, out);
}